// round 8
// baseline (speedup 1.0000x reference)
#include <cuda_runtime.h>
#include <cuda_fp16.h>
#include <cstdint>

// Problem constants
#define M_TOKENS   2048
#define IN_FEAT    2048
#define OUT_FEAT   2048
#define TILE_B     16
#define C_BLOCKS   128
#define R_BLOCKS   128
#define K_BLOCKS   32

// Scratch (allocation-free rule: __device__ globals)
// x packed fp16, fragment-linear: [c (128)][token_group (128)][lane (32)][8 halves]
__device__ __half g_xh[(size_t)C_BLOCKS * (M_TOKENS / 16) * 32 * 8];   // 8 MB
// values packed fp16, B-fragment rows: [r][k][lane (32)][8 halves]
__device__ __half g_vh[(size_t)R_BLOCKS * K_BLOCKS * 32 * 8];          // 2 MB

// ---------------------------------------------------------------------------
__device__ __forceinline__ void cp_async16(uint32_t saddr, const void* gaddr) {
    asm volatile("cp.async.cg.shared.global [%0], [%1], 16;\n"
                 :: "r"(saddr), "l"(gaddr));
}
__device__ __forceinline__ void cp_commit() {
    asm volatile("cp.async.commit_group;\n");
}
template <int N>
__device__ __forceinline__ void cp_wait() {
    asm volatile("cp.async.wait_group %0;\n" :: "n"(N));
}

// ---------------------------------------------------------------------------
// Combined pack kernel.
//  blocks [0, 1024): pack_x — cp.async fp32 staging + fragment assembly.
//  blocks [1024, 1536): pack_v — B-fragment rows, 16B store per thread.
// ---------------------------------------------------------------------------
#define XROWF 260   // floats per smem row (1040 B: 16B-aligned rows)
#define PACKX_BLOCKS 1024
#define PACKV_BLOCKS 512

__global__ __launch_bounds__(256)
void pack_combined_kernel(const float* __restrict__ x,
                          const float* __restrict__ values) {
    __shared__ __align__(16) float sXf[16 * XROWF];   // 16.6 KB

    const int tid = threadIdx.x;

    if (blockIdx.x < PACKX_BLOCKS) {
        const int tg = blockIdx.x >> 3;        // token group 0..127
        const int cg = blockIdx.x & 7;         // c-block group 0..7

        // Phase 1: 16 tokens x 256 floats via cp.async (4 x 16B per thread)
        const uint32_t sbase = (uint32_t)__cvta_generic_to_shared(sXf);
        const float* gx = x + (size_t)(tg * 16) * IN_FEAT + cg * 256;
        #pragma unroll
        for (int i = 0; i < 4; i++) {
            int flat  = i * 256 + tid;         // float4 slot 0..1023
            int token = flat >> 6;
            int cq    = flat & 63;
            cp_async16(sbase + (token * XROWF + cq * 4) * 4,
                       gx + (size_t)token * IN_FEAT + cq * 4);
        }
        cp_commit();
        cp_wait<0>();
        __syncthreads();

        // Phase 2: 512 fragments (16 c_local x 32 lanes); 2 per thread.
        #pragma unroll
        for (int f0 = 0; f0 < 2; f0++) {
            int f    = f0 * 256 + tid;
            int lane = f & 31;
            int cl   = f >> 5;
            __half2 h[4];
            #pragma unroll
            for (int p = 0; p < 4; p++) {
                int t  = (p & 1) * 8 + (lane >> 2);
                int jp = (p >> 1) * 4 + (lane & 3);
                float2 v = *(const float2*)&sXf[t * XROWF + cl * 16 + jp * 2];
                h[p] = __floats2half2_rn(v.x, v.y);
            }
            int c = cg * 16 + cl;
            *(uint4*)(g_xh + (((size_t)c * 128 + tg) * 32 + lane) * 8) =
                *reinterpret_cast<uint4*>(h);
        }
    } else {
        // pack_v: one thread per (r,k,lane)
        int idx = (blockIdx.x - PACKX_BLOCKS) * 256 + tid;   // 0..131071
        int lane = idx & 31;
        int k    = (idx >> 5) & 31;
        int r    = idx >> 10;
        int q    = lane & 3;
        int i    = lane >> 2;
        const float* vp = values + (((size_t)r * K_BLOCKS + k) * TILE_B + i) * TILE_B;
        float2 a0 = *(const float2*)(vp + 2 * q);
        float2 a1 = *(const float2*)(vp + 2 * q + 8);
        const float* vp8 = vp + 8 * TILE_B;
        float2 b0 = *(const float2*)(vp8 + 2 * q);
        float2 b1 = *(const float2*)(vp8 + 2 * q + 8);
        __half2 h[4];
        h[0] = __floats2half2_rn(a0.x, a0.y);
        h[1] = __floats2half2_rn(a1.x, a1.y);
        h[2] = __floats2half2_rn(b0.x, b0.y);
        h[3] = __floats2half2_rn(b1.x, b1.y);
        *(uint4*)(g_vh + (size_t)idx * 8) = *reinterpret_cast<uint4*>(h);
    }
}

// ---------------------------------------------------------------------------
__device__ __forceinline__ void mma16816(float* c, const uint4& a, const uint2& b) {
    asm volatile(
        "mma.sync.aligned.m16n8k16.row.col.f32.f16.f16.f32 "
        "{%0,%1,%2,%3}, {%4,%5,%6,%7}, {%8,%9}, {%0,%1,%2,%3};\n"
        : "+f"(c[0]), "+f"(c[1]), "+f"(c[2]), "+f"(c[3])
        : "r"(a.x), "r"(a.y), "r"(a.z), "r"(a.w), "r"(b.x), "r"(b.y));
}

__device__ __forceinline__ uint4 ldgA(int c, int tg, int lane) {
    return __ldg((const uint4*)(g_xh + (((size_t)c * 128 + tg) * 32 + lane) * 8));
}

// ---------------------------------------------------------------------------
// Main: CTA = (256-token tile, one r). grid (8,128)=1024, 256 thr.
// Warp w owns token groups tg0 = bx*16 + 2w, tg0+1. A fragments LDG'd
// directly from L2-resident packed x, register pipeline depth 2. V[r]
// (16 KB) smem-resident. Zero syncs in the k-loop.
// ---------------------------------------------------------------------------
#define SV_HALVES (K_BLOCKS * 32 * 8)    // 8192 halves = 16 KB

__global__ __launch_bounds__(256, 4)
void cms_main_kernel(const int* __restrict__ col_indices,
                     const float* __restrict__ bias,
                     float* __restrict__ out) {
    __shared__ __align__(16) __half sV[SV_HALVES];   // 16 KB
    __shared__ int s_col[K_BLOCKS + 2];              // padded for prefetch clamp

    const int bx   = blockIdx.x;          // token tile (256 tokens)
    const int r    = blockIdx.y;
    const int tid  = threadIdx.x;
    const int w    = tid >> 5;
    const int lane = tid & 31;
    const int tg0  = bx * 16 + w * 2;

    if (tid < K_BLOCKS) s_col[tid] = col_indices[r * K_BLOCKS + tid];
    if (tid < 2)        s_col[K_BLOCKS + tid] = col_indices[r * K_BLOCKS + K_BLOCKS - 1];

    // bias for this warp's 16 output features (hoisted)
    const int gq = lane & 3;
    float bv[2][2];
    #pragma unroll
    for (int nt = 0; nt < 2; nt++) {
        int f = r * TILE_B + nt * 8 + gq * 2;
        bv[nt][0] = __ldg(bias + f);
        bv[nt][1] = __ldg(bias + f + 1);
    }

    // V[r]: 16 KB contiguous via cp.async
    const uint32_t sv_base = (uint32_t)__cvta_generic_to_shared(sV);
    const __half* gv = g_vh + (size_t)r * SV_HALVES;
    #pragma unroll
    for (int i = 0; i < 4; i++) {
        int chunk = i * 256 + tid;
        cp_async16(sv_base + chunk * 16, gv + chunk * 8);
    }
    cp_commit();
    __syncthreads();   // s_col visible

    // A register pipeline, depth 2, for 2 token groups
    uint4 ap0[2], ap1[2];
    {
        int c0 = s_col[0], c1 = s_col[1];
        ap0[0] = ldgA(c0, tg0, lane);     ap1[0] = ldgA(c0, tg0 + 1, lane);
        ap0[1] = ldgA(c1, tg0, lane);     ap1[1] = ldgA(c1, tg0 + 1, lane);
    }

    float acc[2][8];
    #pragma unroll
    for (int mt = 0; mt < 2; mt++)
        #pragma unroll
        for (int i = 0; i < 8; i++) acc[mt][i] = 0.0f;

    cp_wait<0>();
    __syncthreads();   // V visible

    #pragma unroll 4
    for (int k = 0; k < K_BLOCKS; k++) {
        uint4 a0 = ap0[k & 1];
        uint4 a1 = ap1[k & 1];
        int cn = s_col[k + 2];            // clamped pad beyond 31
        ap0[k & 1] = ldgA(cn, tg0, lane);
        ap1[k & 1] = ldgA(cn, tg0 + 1, lane);

        uint4 vb = *(const uint4*)&sV[((size_t)k * 32 + lane) * 8];
        uint2 b0 = make_uint2(vb.x, vb.y);
        uint2 b1 = make_uint2(vb.z, vb.w);

        mma16816(acc[0] + 0, a0, b0);
        mma16816(acc[0] + 4, a0, b1);
        mma16816(acc[1] + 0, a1, b0);
        mma16816(acc[1] + 4, a1, b1);
    }

    // Epilogue: 2 token groups x 16 cols
    const int gr = lane >> 2;
    #pragma unroll
    for (int mt = 0; mt < 2; mt++) {
        int token0 = (tg0 + mt) * 16;
        #pragma unroll
        for (int nt = 0; nt < 2; nt++) {
            int f = r * TILE_B + nt * 8 + gq * 2;
            const float* a = acc[mt] + nt * 4;
            float* o0 = out + (size_t)(token0 + gr) * OUT_FEAT + f;
            o0[0] = a[0] + bv[nt][0];
            o0[1] = a[1] + bv[nt][1];
            float* o1 = out + (size_t)(token0 + gr + 8) * OUT_FEAT + f;
            o1[0] = a[2] + bv[nt][0];
            o1[1] = a[3] + bv[nt][1];
        }
    }
}

// ---------------------------------------------------------------------------
extern "C" void kernel_launch(void* const* d_in, const int* in_sizes, int n_in,
                              void* d_out, int out_size) {
    const float* x      = (const float*)d_in[0];
    const float* values = (const float*)d_in[1];
    const int*   col    = (const int*)d_in[2];
    const float* bias   = (const float*)d_in[3];
    float*       out    = (float*)d_out;

    (void)in_sizes; (void)n_in; (void)out_size;

    pack_combined_kernel<<<PACKX_BLOCKS + PACKV_BLOCKS, 256>>>(x, values);
    cms_main_kernel<<<dim3(M_TOKENS / 256, R_BLOCKS), 256>>>(col, bias, out);
}